// round 2
// baseline (speedup 1.0000x reference)
#include <cuda_runtime.h>

#define N_NODES 100000
#define N_EDGES 3200000
#define HID 32
#define NCONV 16

// ---- device scratch (static globals; no allocation) ----
__device__ int   g_deg[N_NODES];
__device__ int   g_cursor[N_NODES];
__device__ int   g_rowptr[N_NODES + 1];
__device__ float g_invdeg[N_NODES];
__device__ int   g_csr[N_EDGES];
__device__ float g_bufA[N_NODES * HID];
__device__ float g_bufB[N_NODES * HID];
__device__ float g_colsum[(NCONV + 1) * HID];
__device__ float g_zexp[N_NODES];
__device__ float g_S[1];
__device__ int   g_is64;

// ---------------------------------------------------------------------------
// dtype detect: if edge_index is int64 (LE), every odd 32-bit word is 0
// (values in [0, 1e5)). If int32, odd words are random node ids.
__global__ void detect_kernel(const unsigned int* __restrict__ raw) {
    __shared__ int any;
    if (threadIdx.x == 0) any = 0;
    __syncthreads();
    // sample 64 odd words spread across the buffer (int32 length 2*N_EDGES)
    unsigned v = raw[2 * threadIdx.x + 1 + threadIdx.x * 9973 * 2];
    if (v != 0u) atomicOr(&any, 1);
    __syncthreads();
    if (threadIdx.x == 0) g_is64 = any ? 0 : 1;
}

// init: zero deg/cursor, colsum (layer0 scale = 1), S
__global__ void init_kernel() {
    int i = blockIdx.x * blockDim.x + threadIdx.x;
    if (i < N_NODES) { g_deg[i] = 0; g_cursor[i] = 0; }
    if (i < (NCONV + 1) * HID) g_colsum[i] = (i < HID) ? 1.0f : 0.0f;
    if (i == 0) g_S[0] = 0.0f;
}

__device__ __forceinline__ int load_edge(const void* p, long long idx) {
    if (g_is64) return (int)((const long long*)p)[idx];
    return ((const int*)p)[idx];
}

// histogram of dst
__global__ void hist_kernel(const void* __restrict__ ei) {
    int i = blockIdx.x * blockDim.x + threadIdx.x;
    if (i < N_EDGES) {
        int d = load_edge(ei, (long long)N_EDGES + i);
        if ((unsigned)d < N_NODES) atomicAdd(&g_deg[d], 1);
    }
}

// single-block exclusive scan of deg -> rowptr, plus inv_deg
__global__ void scan_kernel() {
    const int T = 1024;
    const int C = (N_NODES + T - 1) / T;  // 98
    int t = threadIdx.x;
    int beg = t * C;
    int end = min(beg + C, N_NODES);
    int local = 0;
    for (int i = beg; i < end; ++i) local += g_deg[i];

    int lane = t & 31, w = t >> 5;
    int v = local;
#pragma unroll
    for (int o = 1; o < 32; o <<= 1) {
        int u = __shfl_up_sync(0xffffffffu, v, o);
        if (lane >= o) v += u;
    }
    __shared__ int wsum[32];
    if (lane == 31) wsum[w] = v;
    __syncthreads();
    if (w == 0) {
        int s = wsum[lane];
#pragma unroll
        for (int o = 1; o < 32; o <<= 1) {
            int u = __shfl_up_sync(0xffffffffu, s, o);
            if (lane >= o) s += u;
        }
        wsum[lane] = s;
    }
    __syncthreads();
    int off = (v - local) + (w > 0 ? wsum[w - 1] : 0);
    for (int i = beg; i < end; ++i) {
        g_rowptr[i] = off;
        int d = g_deg[i];
        off += d;
        g_invdeg[i] = 1.0f / (float)max(d, 1);
    }
    if (beg < N_NODES && end == N_NODES) g_rowptr[N_NODES] = off;
}

// fill CSR (srcs grouped by dst)
__global__ void fill_kernel(const void* __restrict__ ei) {
    int i = blockIdx.x * blockDim.x + threadIdx.x;
    if (i < N_EDGES) {
        int s = load_edge(ei, i);
        int d = load_edge(ei, (long long)N_EDGES + i);
        if ((unsigned)d >= N_NODES || (unsigned)s >= N_NODES) return;
        int p = atomicAdd(&g_cursor[d], 1);
        g_csr[g_rowptr[d] + p] = s;
    }
}

// ---------------------------------------------------------------------------
// proj_in: x[N,4] -> inner-softmax(avg@A_in + x@B_in) [N,32]. One warp/node.
__global__ void __launch_bounds__(256) proj_kernel(
    const float* __restrict__ x, const float* __restrict__ Ain,
    const float* __restrict__ Bin, float* __restrict__ out) {
    int lane = threadIdx.x & 31, wid = threadIdx.x >> 5;
    int n = blockIdx.x * 8 + wid;
    if (n >= N_NODES) return;
    int beg = g_rowptr[n], end = g_rowptr[n + 1];
    int gb = lane >> 2, ft = lane & 3;  // 8 neighbors per iteration, 4 feats each
    float sum = 0.0f;
    for (int base = beg; base < end; base += 8) {
        int j = base + gb;
        if (j < end) {
            int s = __ldg(&g_csr[j]);
            sum += __ldg(&x[s * 4 + ft]);
        }
    }
    sum += __shfl_xor_sync(0xffffffffu, sum, 4);
    sum += __shfl_xor_sync(0xffffffffu, sum, 8);
    sum += __shfl_xor_sync(0xffffffffu, sum, 16);
    float invd = g_invdeg[n];
    float a0 = __shfl_sync(0xffffffffu, sum, 0) * invd;
    float a1 = __shfl_sync(0xffffffffu, sum, 1) * invd;
    float a2 = __shfl_sync(0xffffffffu, sum, 2) * invd;
    float a3 = __shfl_sync(0xffffffffu, sum, 3) * invd;
    float4 xv = *(const float4*)&x[n * 4];
    float acc = a0 * __ldg(&Ain[lane])      + a1 * __ldg(&Ain[32 + lane])
              + a2 * __ldg(&Ain[64 + lane]) + a3 * __ldg(&Ain[96 + lane])
              + xv.x * __ldg(&Bin[lane])      + xv.y * __ldg(&Bin[32 + lane])
              + xv.z * __ldg(&Bin[64 + lane]) + xv.w * __ldg(&Bin[96 + lane]);
    float mx = acc;
#pragma unroll
    for (int o = 16; o; o >>= 1) mx = fmaxf(mx, __shfl_xor_sync(0xffffffffu, mx, o));
    float e = __expf(acc - mx);
    float ss = e;
#pragma unroll
    for (int o = 16; o; o >>= 1) ss += __shfl_xor_sync(0xffffffffu, ss, o);
    out[n * HID + lane] = e / ss;
}

// ---------------------------------------------------------------------------
// hidden conv layer. Input buffer holds E_prev = exp(p_prev) (or p0 for layer 1);
// cs_in holds its column sums (1.0 for layer 1). Output: E = exp(inner_softmax),
// with column sums accumulated into cs_out. The axis-0 softmax is applied
// lazily via the 1/colsum scale — zero extra memory passes.
__global__ void __launch_bounds__(256) conv_kernel(
    const float* __restrict__ Ein, float* __restrict__ Eout,
    const float* __restrict__ Wa, const float* __restrict__ Wb,
    const float* __restrict__ cs_in, float* __restrict__ cs_out) {
    int lane = threadIdx.x & 31, wid = threadIdx.x >> 5;
    float WaR[HID], WbR[HID];
#pragma unroll
    for (int k = 0; k < HID; ++k) {
        WaR[k] = __ldg(&Wa[k * HID + lane]);
        WbR[k] = __ldg(&Wb[k * HID + lane]);
    }
    float invS = 1.0f / cs_in[lane];
    float colacc = 0.0f;

    for (int n = blockIdx.x * 8 + wid; n < N_NODES; n += gridDim.x * 8) {
        int beg = g_rowptr[n], end = g_rowptr[n + 1];
        float sum = 0.0f;
#pragma unroll 4
        for (int i = beg; i < end; ++i) {
            int s = __ldg(&g_csr[i]);
            sum += __ldg(&Ein[s * HID + lane]);
        }
        float avg = sum * (g_invdeg[n] * invS);
        float xd = __ldg(&Ein[n * HID + lane]) * invS;
        float acc = 0.0f;
#pragma unroll
        for (int k = 0; k < HID; ++k) {
            acc = fmaf(__shfl_sync(0xffffffffu, avg, k), WaR[k], acc);
            acc = fmaf(__shfl_sync(0xffffffffu, xd, k), WbR[k], acc);
        }
        float mx = acc;
#pragma unroll
        for (int o = 16; o; o >>= 1) mx = fmaxf(mx, __shfl_xor_sync(0xffffffffu, mx, o));
        float e = __expf(acc - mx);
        float ss = e;
#pragma unroll
        for (int o = 16; o; o >>= 1) ss += __shfl_xor_sync(0xffffffffu, ss, o);
        float E = __expf(e / ss);
        Eout[n * HID + lane] = E;
        colacc += E;
    }

    __shared__ float sred[8][HID];
    sred[wid][lane] = colacc;
    __syncthreads();
    if (wid == 0) {
        float t = sred[0][lane];
#pragma unroll
        for (int i = 1; i < 8; ++i) t += sred[i][lane];
        atomicAdd(&cs_out[lane], t);
    }
}

// ---------------------------------------------------------------------------
// final: z[n] = sum_k E[n,k]*(Wout[k]/colsum[k]) + b; store exp(z); sum -> S
__global__ void __launch_bounds__(256) out_z_kernel(
    const float* __restrict__ E, const float* __restrict__ cs,
    const float* __restrict__ Wout, const float* __restrict__ bout) {
    int lane = threadIdx.x & 31, wid = threadIdx.x >> 5;
    float w = __ldg(&Wout[lane]) / cs[lane];
    float b = __ldg(bout);
    float acc = 0.0f;
    for (int n = blockIdx.x * 8 + wid; n < N_NODES; n += gridDim.x * 8) {
        float v = E[n * HID + lane] * w;
#pragma unroll
        for (int o = 16; o; o >>= 1) v += __shfl_xor_sync(0xffffffffu, v, o);
        float e = __expf(v + b);
        if (lane == 0) { g_zexp[n] = e; acc += e; }
    }
    __shared__ float sred[8];
    if (lane == 0) sred[wid] = acc;
    __syncthreads();
    if (threadIdx.x == 0) {
        float t = 0.0f;
#pragma unroll
        for (int i = 0; i < 8; ++i) t += sred[i];
        atomicAdd(g_S, t);
    }
}

__global__ void out_norm_kernel(float* __restrict__ out) {
    int i = blockIdx.x * blockDim.x + threadIdx.x;
    if (i < N_NODES) out[i] = g_zexp[i] / g_S[0];
}

// ---------------------------------------------------------------------------
extern "C" void kernel_launch(void* const* d_in, const int* in_sizes, int n_in,
                              void* d_out, int out_size) {
    const float* x        = (const float*)d_in[0];
    const void*  ei       = d_in[1];                    // [2, N_EDGES] int32 or int64
    const float* Ain      = (const float*)d_in[2];
    const float* Bin      = (const float*)d_in[3];
    const float* Aconv    = (const float*)d_in[4];      // [16,32,32]
    const float* Bconv    = (const float*)d_in[5];
    const float* Wout     = (const float*)d_in[6];
    const float* bout     = (const float*)d_in[7];
    float* out            = (float*)d_out;

    float *pA, *pB, *pcs;
    cudaGetSymbolAddress((void**)&pA, g_bufA);
    cudaGetSymbolAddress((void**)&pB, g_bufB);
    cudaGetSymbolAddress((void**)&pcs, g_colsum);

    detect_kernel<<<1, 64>>>((const unsigned int*)ei);
    init_kernel<<<(N_NODES + 255) / 256, 256>>>();
    hist_kernel<<<(N_EDGES + 255) / 256, 256>>>(ei);
    scan_kernel<<<1, 1024>>>();
    fill_kernel<<<(N_EDGES + 255) / 256, 256>>>(ei);

    proj_kernel<<<(N_NODES + 7) / 8, 256>>>(x, Ain, Bin, pA);

    float* bi = pA;
    float* bo = pB;
    for (int l = 0; l < NCONV; ++l) {
        conv_kernel<<<1184, 256>>>(bi, bo,
                                   Aconv + l * HID * HID, Bconv + l * HID * HID,
                                   pcs + l * HID, pcs + (l + 1) * HID);
        float* t = bi; bi = bo; bo = t;
    }

    out_z_kernel<<<592, 256>>>(bi, pcs + NCONV * HID, Wout, bout);
    out_norm_kernel<<<(N_NODES + 255) / 256, 256>>>(out);
}